// round 1
// baseline (speedup 1.0000x reference)
#include <cuda_runtime.h>
#include <math.h>
#include <stdint.h>

#define Bsz 32
#define Nn  500
#define Gg  500
#define Hh  128
#define KNB 16

// ---------------- scratch (device globals; no allocation) ----------------
__device__ float g_qgraph[Bsz*Hh];          // (B,128)
__device__ float g_Wall[Hh*384];            // [k][j]: j<128 Wk^T, <256 Wv^T, <384 Wc
__device__ float g_WqT[Hh*Hh];              // [k][o] = Wq_first[o][k]+Wq_last[o][k]
__device__ float g_embT[Bsz*Hh*Nn];         // (B,128,N)  k-major embeddings
__device__ float g_lastT[Bsz*Hh*Gg];        // (B,128,G)  k-major gathered last_emb
__device__ float g_K[(size_t)Bsz*Nn*Hh];    // (B,N,128)
__device__ float g_V[(size_t)Bsz*Nn*Hh];    // (B,N,128)
__device__ float g_EpT[Bsz*Hh*Nn];          // (B,128,N)  E' = emb@Wc, k-major
__device__ float g_biasE[Bsz*Nn];           // bc . emb[b,n]
__device__ float g_Q[(size_t)Bsz*Gg*Hh];    // (B,G,128)
__device__ float g_attnT[Bsz*Hh*Gg];        // (B,128,G)  attention output, k-major

// ---------------- weight prep ----------------
__global__ void wprep_kernel(const float* __restrict__ Wk, const float* __restrict__ Wv,
                             const float* __restrict__ Wc, const float* __restrict__ Wqf,
                             const float* __restrict__ Wql) {
    int idx = blockIdx.x * blockDim.x + threadIdx.x;
    const int total1 = Hh * 384;
    if (idx < total1) {
        int k = idx / 384, j = idx % 384;
        float v;
        if (j < 128)      v = Wk[j*128 + k];
        else if (j < 256) v = Wv[(j-128)*128 + k];
        else              v = Wc[k*128 + (j-256)];
        g_Wall[idx] = v;
    }
    int idx2 = idx - total1;
    if (idx2 >= 0 && idx2 < Hh*Hh) {
        int k = idx2 / 128, o = idx2 % 128;
        g_WqT[idx2] = Wqf[o*128 + k] + Wql[o*128 + k];
    }
}

// ---------------- q_graph = mean(emb) @ Wq_graph^T ----------------
__global__ void qgraph_kernel(const float* __restrict__ emb, const float* __restrict__ Wqg) {
    __shared__ float mean_s[128];
    int b = blockIdx.x, t = threadIdx.x;
    float s = 0.f;
    for (int n = 0; n < Nn; ++n) s += emb[((size_t)b*Nn + n)*Hh + t];
    mean_s[t] = s / (float)Nn;
    __syncthreads();
    float q = 0.f;
#pragma unroll 8
    for (int i = 0; i < 128; ++i) q += mean_s[i] * Wqg[t*128 + i];
    g_qgraph[b*128 + t] = q;
}

// ---------------- transpose emb -> embT (B,128,N) ----------------
__global__ void embT_kernel(const float* __restrict__ emb) {
    __shared__ float tile[32][33];
    int b = blockIdx.z;
    int n0 = blockIdx.x * 32, k0 = blockIdx.y * 32;
    int tx = threadIdx.x, ty = threadIdx.y;
    for (int i = 0; i < 32; i += 8) {
        int n = n0 + ty + i;
        if (n < Nn) tile[ty+i][tx] = emb[((size_t)b*Nn + n)*Hh + k0 + tx];
    }
    __syncthreads();
    for (int i = 0; i < 32; i += 8) {
        int k = k0 + ty + i, n = n0 + tx;
        if (n < Nn) g_embT[(size_t)b*Hh*Nn + k*Nn + n] = tile[tx][ty+i];
    }
}

// ---------------- gather last_emb + transpose -> lastT (B,128,G) ----------------
__global__ void lastT_kernel(const float* __restrict__ emb, const int* __restrict__ last) {
    __shared__ float tile[32][33];
    int b = blockIdx.z;
    int g0 = blockIdx.x * 32, k0 = blockIdx.y * 32;
    int tx = threadIdx.x, ty = threadIdx.y;
    for (int i = 0; i < 32; i += 8) {
        int g = g0 + ty + i;
        if (g < Gg) {
            int row = last[b*Gg + g];
            tile[ty+i][tx] = emb[((size_t)b*Nn + row)*Hh + k0 + tx];
        }
    }
    __syncthreads();
    for (int i = 0; i < 32; i += 8) {
        int k = k0 + ty + i, g = g0 + tx;
        if (g < Gg) g_lastT[(size_t)b*Hh*Gg + k*Gg + g] = tile[tx][ty+i];
    }
}

// ---------------- biasE[b,n] = bc . emb[b,n] ----------------
__global__ void biasE_kernel(const float* __restrict__ emb, const float* __restrict__ bc) {
    int warp = threadIdx.x >> 5, lane = threadIdx.x & 31;
    int r = blockIdx.x * 8 + warp;
    if (r >= Bsz*Nn) return;
    float s = 0.f;
    for (int i = lane; i < 128; i += 32) s += emb[(size_t)r*128 + i] * bc[i];
    for (int off = 16; off; off >>= 1) s += __shfl_xor_sync(0xffffffffu, s, off);
    if (lane == 0) g_biasE[r] = s;
}

// ---------------- GEMM-A: [N x 128] @ [128 x 384] -> K | V | E' ----------------
__global__ __launch_bounds__(256) void gemmA_kernel() {
    extern __shared__ float sm[];
    float* As  = sm;          // [128][64]
    float* Bsm = sm + 8192;   // [128][64]
    int b = blockIdx.z, n0 = blockIdx.y * 64, c0 = blockIdx.x * 64;
    int tid = threadIdx.x;
    const float* embTb = g_embT + (size_t)b*Hh*Nn;
    for (int idx = tid; idx < 8192; idx += 256) {
        int k = idx >> 6, j = idx & 63, n = n0 + j;
        As[idx] = (n < Nn) ? embTb[k*Nn + n] : 0.f;
    }
    for (int idx = tid; idx < 8192; idx += 256) {
        int k = idx >> 6, j = idx & 63;
        Bsm[idx] = g_Wall[k*384 + c0 + j];
    }
    __syncthreads();
    int ty = tid >> 4, tx = tid & 15;
    float acc[4][4] = {};
#pragma unroll 8
    for (int k = 0; k < 128; ++k) {
        float4 a = *(const float4*)(As  + k*64 + ty*4);
        float4 c = *(const float4*)(Bsm + k*64 + tx*4);
        acc[0][0]+=a.x*c.x; acc[0][1]+=a.x*c.y; acc[0][2]+=a.x*c.z; acc[0][3]+=a.x*c.w;
        acc[1][0]+=a.y*c.x; acc[1][1]+=a.y*c.y; acc[1][2]+=a.y*c.z; acc[1][3]+=a.y*c.w;
        acc[2][0]+=a.z*c.x; acc[2][1]+=a.z*c.y; acc[2][2]+=a.z*c.z; acc[2][3]+=a.z*c.w;
        acc[3][0]+=a.w*c.x; acc[3][1]+=a.w*c.y; acc[3][2]+=a.w*c.z; acc[3][3]+=a.w*c.w;
    }
#pragma unroll
    for (int ii = 0; ii < 4; ++ii) {
        int r = n0 + ty*4 + ii;
        if (r >= Nn) continue;
        size_t rowbase = ((size_t)b*Nn + r)*Hh;
#pragma unroll
        for (int jj = 0; jj < 4; ++jj) {
            int c = c0 + tx*4 + jj;
            float v = acc[ii][jj];
            if (c < 128)       g_K[rowbase + c] = v;
            else if (c < 256)  g_V[rowbase + (c-128)] = v;
            else               g_EpT[(size_t)b*Hh*Nn + (c-256)*Nn + r] = v;
        }
    }
}

// ---------------- GEMM-Q: lastT @ WqT + q_graph -> Q (B,G,128) ----------------
__global__ __launch_bounds__(256) void gemmQ_kernel() {
    extern __shared__ float sm[];
    float* As  = sm;
    float* Bsm = sm + 8192;
    int b = blockIdx.z, g0 = blockIdx.y * 64, c0 = blockIdx.x * 64;
    int tid = threadIdx.x;
    const float* lastTb = g_lastT + (size_t)b*Hh*Gg;
    for (int idx = tid; idx < 8192; idx += 256) {
        int k = idx >> 6, j = idx & 63, g = g0 + j;
        As[idx] = (g < Gg) ? lastTb[k*Gg + g] : 0.f;
    }
    for (int idx = tid; idx < 8192; idx += 256) {
        int k = idx >> 6, j = idx & 63;
        Bsm[idx] = g_WqT[k*128 + c0 + j];
    }
    __syncthreads();
    int ty = tid >> 4, tx = tid & 15;
    float acc[4][4] = {};
#pragma unroll 8
    for (int k = 0; k < 128; ++k) {
        float4 a = *(const float4*)(As  + k*64 + ty*4);
        float4 c = *(const float4*)(Bsm + k*64 + tx*4);
        acc[0][0]+=a.x*c.x; acc[0][1]+=a.x*c.y; acc[0][2]+=a.x*c.z; acc[0][3]+=a.x*c.w;
        acc[1][0]+=a.y*c.x; acc[1][1]+=a.y*c.y; acc[1][2]+=a.y*c.z; acc[1][3]+=a.y*c.w;
        acc[2][0]+=a.z*c.x; acc[2][1]+=a.z*c.y; acc[2][2]+=a.z*c.z; acc[2][3]+=a.z*c.w;
        acc[3][0]+=a.w*c.x; acc[3][1]+=a.w*c.y; acc[3][2]+=a.w*c.z; acc[3][3]+=a.w*c.w;
    }
#pragma unroll
    for (int ii = 0; ii < 4; ++ii) {
        int r = g0 + ty*4 + ii;
        if (r >= Gg) continue;
        size_t rowbase = ((size_t)b*Gg + r)*Hh;
#pragma unroll
        for (int jj = 0; jj < 4; ++jj) {
            int c = c0 + tx*4 + jj;
            g_Q[rowbase + c] = acc[ii][jj] + g_qgraph[b*128 + c];
        }
    }
}

// ---------------- glimpse: top-16 neighbors + sparse attention ----------------
__global__ __launch_bounds__(128) void glimpse_kernel(const float* __restrict__ coords,
                                                      const float* __restrict__ mask,
                                                      const int* __restrict__ last) {
    __shared__ float ds[512];
    __shared__ unsigned long long red[4];
    __shared__ int   sel[KNB];
    __shared__ float vsh[KNB*128];
    __shared__ float ssc[128];
    __shared__ float wsh[128];
    int g = blockIdx.x, b = blockIdx.y;
    int tid = threadIdx.x;

    int idxLast = last[b*Gg + g];
    float lx = coords[((size_t)b*Nn + idxLast)*2 + 0];
    float ly = coords[((size_t)b*Nn + idxLast)*2 + 1];

    for (int n = tid; n < 512; n += 128) {
        float d;
        if (n < Nn) {
            float m = mask[((size_t)b*Gg + g)*Nn + n];
            if (m == -INFINITY) d = INFINITY;
            else {
                float dx = lx - coords[((size_t)b*Nn + n)*2 + 0];
                float dy = ly - coords[((size_t)b*Nn + n)*2 + 1];
                d = sqrtf(dx*dx + dy*dy);   // match reference: compare sqrt'd dists
            }
        } else d = INFINITY;
        ds[n] = d;
    }
    __syncthreads();

    // 16 argmin passes, tie-break lowest index (matches lax.top_k stability)
    for (int it = 0; it < KNB; ++it) {
        unsigned long long best = ~0ull;
        for (int n = tid; n < 512; n += 128) {
            unsigned long long key = ((unsigned long long)__float_as_uint(ds[n]) << 32) | (unsigned)n;
            best = min(best, key);
        }
        for (int off = 16; off; off >>= 1)
            best = min(best, __shfl_xor_sync(0xffffffffu, best, off));
        if ((tid & 31) == 0) red[tid >> 5] = best;
        __syncthreads();
        if (tid == 0) {
            unsigned long long m = min(min(red[0], red[1]), min(red[2], red[3]));
            int n = (int)(m & 0xffffffffu);
            sel[it] = n;
            ds[n] = INFINITY;
        }
        __syncthreads();
    }

    // scores over the 16 neighbors (head h = tid/16, dim = tid%16)
    float q = g_Q[((size_t)b*Gg + g)*Hh + tid];
#pragma unroll
    for (int j = 0; j < KNB; ++j) {
        int n = sel[j];
        size_t base = ((size_t)b*Nn + n)*Hh;
        float kv = g_K[base + tid];
        vsh[j*128 + tid] = g_V[base + tid];
        float p = q * kv;
        p += __shfl_xor_sync(0xffffffffu, p, 8, 16);
        p += __shfl_xor_sync(0xffffffffu, p, 4, 16);
        p += __shfl_xor_sync(0xffffffffu, p, 2, 16);
        p += __shfl_xor_sync(0xffffffffu, p, 1, 16);
        if ((tid & 15) == 0) ssc[(tid >> 4)*16 + j] = p * 0.25f;  // 1/sqrt(16)
    }
    __syncthreads();

    if (tid < 8) {
        float mx = -INFINITY;
#pragma unroll
        for (int j = 0; j < KNB; ++j) mx = fmaxf(mx, ssc[tid*16 + j]);
        float s = 0.f;
#pragma unroll
        for (int j = 0; j < KNB; ++j) { float e = expf(ssc[tid*16 + j] - mx); wsh[tid*16 + j] = e; s += e; }
        float inv = 1.f / s;
#pragma unroll
        for (int j = 0; j < KNB; ++j) wsh[tid*16 + j] *= inv;
    }
    __syncthreads();

    int h = tid >> 4;
    float o = 0.f;
#pragma unroll
    for (int j = 0; j < KNB; ++j) o += wsh[h*16 + j] * vsh[j*128 + tid];
    g_attnT[(size_t)b*Hh*Gg + tid*Gg + g] = o;
}

// ---------------- fused pointer GEMM + tanh + mask + row softmax ----------------
__global__ __launch_bounds__(256) void final_kernel(const float* __restrict__ mask,
                                                    float* __restrict__ out) {
    extern __shared__ float sm[];
    float* As  = sm;            // [128][64]  attnT tile
    float* Bsm = sm + 8192;     // [128][64]  E' tile
    float* sc  = sm + 16384;    // [64][512]  scores
    int b = blockIdx.y, g0 = blockIdx.x * 64;
    int tid = threadIdx.x;
    const float* attnTb = g_attnT + (size_t)b*Hh*Gg;
    for (int idx = tid; idx < 8192; idx += 256) {
        int k = idx >> 6, j = idx & 63, g = g0 + j;
        As[idx] = (g < Gg) ? attnTb[k*Gg + g] : 0.f;
    }
    int ty = tid >> 4, tx = tid & 15;

    for (int t = 0; t < 8; ++t) {
        int n0 = t * 64;
        for (int idx = tid; idx < 8192; idx += 256) {
            int k = idx >> 6, j = idx & 63, n = n0 + j;
            Bsm[idx] = (n < Nn) ? g_EpT[(size_t)b*Hh*Nn + k*Nn + n] : 0.f;
        }
        __syncthreads();
        float acc[4][4] = {};
#pragma unroll 8
        for (int k = 0; k < 128; ++k) {
            float4 a = *(const float4*)(As  + k*64 + ty*4);
            float4 c = *(const float4*)(Bsm + k*64 + tx*4);
            acc[0][0]+=a.x*c.x; acc[0][1]+=a.x*c.y; acc[0][2]+=a.x*c.z; acc[0][3]+=a.x*c.w;
            acc[1][0]+=a.y*c.x; acc[1][1]+=a.y*c.y; acc[1][2]+=a.y*c.z; acc[1][3]+=a.y*c.w;
            acc[2][0]+=a.z*c.x; acc[2][1]+=a.z*c.y; acc[2][2]+=a.z*c.z; acc[2][3]+=a.z*c.w;
            acc[3][0]+=a.w*c.x; acc[3][1]+=a.w*c.y; acc[3][2]+=a.w*c.z; acc[3][3]+=a.w*c.w;
        }
#pragma unroll
        for (int ii = 0; ii < 4; ++ii) {
            int g = g0 + ty*4 + ii;
            if (g >= Gg) continue;
            const float* mrow = mask + ((size_t)b*Gg + g)*Nn;
#pragma unroll
            for (int jj = 0; jj < 4; ++jj) {
                int n = n0 + tx*4 + jj;
                if (n >= Nn) continue;
                float s = acc[ii][jj] + g_biasE[b*Nn + n];
                sc[(ty*4 + ii)*512 + n] = tanhf(s) * 10.0f + mrow[n];
            }
        }
        __syncthreads();
    }

    // row softmax over N, 8 rows per warp
    int warp = tid >> 5, lane = tid & 31;
    for (int gr = warp; gr < 64; gr += 8) {
        int g = g0 + gr;
        if (g >= Gg) continue;
        float* row = sc + gr*512;
        float m = -INFINITY;
        for (int n = lane; n < Nn; n += 32) m = fmaxf(m, row[n]);
        for (int off = 16; off; off >>= 1) m = fmaxf(m, __shfl_xor_sync(0xffffffffu, m, off));
        float s = 0.f;
        for (int n = lane; n < Nn; n += 32) { float e = expf(row[n] - m); row[n] = e; s += e; }
        for (int off = 16; off; off >>= 1) s += __shfl_xor_sync(0xffffffffu, s, off);
        float inv = 1.f / s;
        float* orow = out + ((size_t)b*Gg + g)*Nn;
        for (int n = lane; n < Nn; n += 32) orow[n] = row[n] * inv;
    }
}

// ---------------- host ----------------
extern "C" void kernel_launch(void* const* d_in, const int* in_sizes, int n_in,
                              void* d_out, int out_size) {
    const float* coords   = (const float*)d_in[0];
    const float* emb      = (const float*)d_in[1];
    const int*   last     = (const int*)  d_in[2];
    const float* mask     = (const float*)d_in[3];
    const float* Wq_graph = (const float*)d_in[4];
    const float* Wq_first = (const float*)d_in[5];
    const float* Wq_last  = (const float*)d_in[6];
    const float* Wk       = (const float*)d_in[7];
    const float* Wv       = (const float*)d_in[8];
    const float* Wc       = (const float*)d_in[9];
    const float* bc       = (const float*)d_in[10];
    float* out = (float*)d_out;

    cudaFuncSetAttribute(gemmA_kernel, cudaFuncAttributeMaxDynamicSharedMemorySize, 65536);
    cudaFuncSetAttribute(gemmQ_kernel, cudaFuncAttributeMaxDynamicSharedMemorySize, 65536);
    cudaFuncSetAttribute(final_kernel, cudaFuncAttributeMaxDynamicSharedMemorySize, 196608);

    wprep_kernel<<<256, 256>>>(Wk, Wv, Wc, Wq_first, Wq_last);
    qgraph_kernel<<<Bsz, 128>>>(emb, Wq_graph);
    embT_kernel<<<dim3(16, 4, Bsz), dim3(32, 8)>>>(emb);
    lastT_kernel<<<dim3(16, 4, Bsz), dim3(32, 8)>>>(emb, last);
    biasE_kernel<<<(Bsz*Nn + 7) / 8, 256>>>(emb, bc);
    gemmA_kernel<<<dim3(6, 8, Bsz), 256, 65536>>>();
    gemmQ_kernel<<<dim3(2, 8, Bsz), 256, 65536>>>();
    glimpse_kernel<<<dim3(Gg, Bsz), 128>>>(coords, mask, last);
    final_kernel<<<dim3(8, Bsz), 256, 196608>>>(mask, out);
}

// round 4
// speedup vs baseline: 1.2680x; 1.2680x over previous
#include <cuda_runtime.h>
#include <math.h>
#include <stdint.h>

#define Bsz 32
#define Nn  500
#define Gg  500
#define Hh  128
#define KNB 16

// ---------------- scratch (device globals; no allocation) ----------------
__device__ float g_qgraph[Bsz*Hh];           // (B,128)
__device__ float g_colsum[Bsz*Hh];           // column sums of emb (for mean)
__device__ float g_Wall[Hh*384];             // [k][j]: j<128 Wk^T, <256 Wv^T, <384 Wc
__device__ float g_WqT[Hh*Hh];               // [k][o] = Wq_first[o][k]+Wq_last[o][k]
__device__ float g_embT[Bsz*Hh*Nn];          // (B,128,N)  k-major embeddings
__device__ float g_lastT[Bsz*Hh*Gg];         // (B,128,G)  k-major gathered last_emb
__device__ float g_K[(size_t)Bsz*Nn*Hh];     // (B,N,128)
__device__ float g_V[(size_t)Bsz*Nn*Hh];     // (B,N,128)
__device__ float g_EpT[Bsz*Hh*Nn];           // (B,128,N)  E' = emb@Wc, k-major
__device__ float g_biasE[Bsz*Nn];            // bc . emb[b,n]
__device__ float g_Q[(size_t)Bsz*Gg*Hh];     // (B,G,128)
__device__ float g_attnT[Bsz*Hh*Gg];         // (B,128,G)  attention output, k-major

// ---------------- f32x2 packed-FMA helpers ----------------
__device__ __forceinline__ void ffma2(unsigned long long &d,
                                      unsigned long long a,
                                      unsigned long long b) {
    asm("fma.rn.f32x2 %0, %1, %2, %0;" : "+l"(d) : "l"(a), "l"(b));
}
__device__ __forceinline__ unsigned long long bpack(float x) {
    unsigned long long r;
    asm("mov.b64 %0, {%1, %1};" : "=l"(r) : "f"(x));
    return r;
}
__device__ __forceinline__ void unpack2(unsigned long long v, float &lo, float &hi) {
    asm("mov.b64 {%0, %1}, %2;" : "=f"(lo), "=f"(hi) : "l"(v));
}

// 128x128x128 tile, 256 threads, 8x8 micro-tile, f32x2 packed accumulation.
// As/Bs: [128 k][128 cols] row-major in smem. acc[rp][c]: rp=row-pair, c=col.
__device__ __forceinline__ void mm_8x8(const float* __restrict__ As,
                                       const float* __restrict__ Bs,
                                       int ty, int tx,
                                       unsigned long long acc[4][8]) {
#pragma unroll 8
    for (int k = 0; k < 128; ++k) {
        ulonglong2 aA = *(const ulonglong2*)(As + k*128 + ty*8);
        ulonglong2 aB = *(const ulonglong2*)(As + k*128 + ty*8 + 4);
        float4 b0 = *(const float4*)(Bs + k*128 + tx*8);
        float4 b1 = *(const float4*)(Bs + k*128 + tx*8 + 4);
        unsigned long long bb[8];
        bb[0]=bpack(b0.x); bb[1]=bpack(b0.y); bb[2]=bpack(b0.z); bb[3]=bpack(b0.w);
        bb[4]=bpack(b1.x); bb[5]=bpack(b1.y); bb[6]=bpack(b1.z); bb[7]=bpack(b1.w);
#pragma unroll
        for (int c = 0; c < 8; ++c) {
            ffma2(acc[0][c], aA.x, bb[c]);
            ffma2(acc[1][c], aA.y, bb[c]);
            ffma2(acc[2][c], aB.x, bb[c]);
            ffma2(acc[3][c], aB.y, bb[c]);
        }
    }
}

__device__ __forceinline__ void unpack_acc(unsigned long long acc[4][8], float accf[8][8]) {
#pragma unroll
    for (int rp = 0; rp < 4; ++rp)
#pragma unroll
        for (int c = 0; c < 8; ++c)
            unpack2(acc[rp][c], accf[2*rp][c], accf[2*rp+1][c]);
}

// load a [128 k][128 j] tile from k-major source with row pitch `pitch`,
// columns j0..j0+127 guarded against jmax
__device__ __forceinline__ void load_tile(float* __restrict__ dst,
                                          const float* __restrict__ src,
                                          int pitch, int j0, int jmax, int tid) {
    for (int s = tid; s < 4096; s += 256) {
        int k = s >> 5, j = (s & 31) * 4;
        float4 v;
        int n = j0 + j;
        if (n + 3 < jmax) {
            v = *(const float4*)(src + (size_t)k*pitch + n);
        } else {
            float t0=0.f, t1=0.f, t2=0.f, t3=0.f;
            if (n     < jmax) t0 = src[(size_t)k*pitch + n];
            if (n + 1 < jmax) t1 = src[(size_t)k*pitch + n + 1];
            if (n + 2 < jmax) t2 = src[(size_t)k*pitch + n + 2];
            if (n + 3 < jmax) t3 = src[(size_t)k*pitch + n + 3];
            v = make_float4(t0, t1, t2, t3);
        }
        *(float4*)(dst + k*128 + j) = v;
    }
}

// ---------------- weight prep + zero accumulators ----------------
__global__ void wprep_kernel(const float* __restrict__ Wk, const float* __restrict__ Wv,
                             const float* __restrict__ Wc, const float* __restrict__ Wqf,
                             const float* __restrict__ Wql) {
    int idx = blockIdx.x * blockDim.x + threadIdx.x;
    const int total1 = Hh * 384;
    if (idx < total1) {
        int k = idx / 384, j = idx % 384;
        float v;
        if (j < 128)      v = Wk[j*128 + k];
        else if (j < 256) v = Wv[(j-128)*128 + k];
        else              v = Wc[k*128 + (j-256)];
        g_Wall[idx] = v;
    }
    int idx2 = idx - total1;
    if (idx2 >= 0 && idx2 < Hh*Hh) {
        int k = idx2 / 128, o = idx2 % 128;
        g_WqT[idx2] = Wqf[o*128 + k] + Wql[o*128 + k];
    }
    if (idx < Bsz*Hh) g_colsum[idx] = 0.f;
    if (idx < Bsz*Nn) g_biasE[idx] = 0.f;
}

// ---------------- transpose emb -> embT + fold column-sum + biasE ----------------
__global__ void embT_kernel(const float* __restrict__ emb, const float* __restrict__ bc) {
    __shared__ float tile[32][33];
    int b = blockIdx.z;
    int n0 = blockIdx.x * 32, k0 = blockIdx.y * 32;
    int tx = threadIdx.x, ty = threadIdx.y;
    float bcv = bc[k0 + tx];
    float csum = 0.f;
#pragma unroll
    for (int i = 0; i < 32; i += 8) {
        int n = n0 + ty + i;
        float v = 0.f;
        if (n < Nn) {
            v = emb[((size_t)b*Nn + n)*Hh + k0 + tx];
            tile[ty+i][tx] = v;
        }
        csum += v;
        // biasE partial: reduce v*bc over the warp (all lanes share row n)
        float contrib = v * bcv;
        for (int off = 16; off; off >>= 1)
            contrib += __shfl_xor_sync(0xffffffffu, contrib, off);
        if (tx == 0 && n < Nn) atomicAdd(&g_biasE[b*Nn + n], contrib);
    }
    atomicAdd(&g_colsum[b*128 + k0 + tx], csum);
    __syncthreads();
#pragma unroll
    for (int i = 0; i < 32; i += 8) {
        int k = k0 + ty + i, n = n0 + tx;
        if (n < Nn) g_embT[(size_t)b*Hh*Nn + k*Nn + n] = tile[tx][ty+i];
    }
}

// ---------------- gather last_emb + transpose -> lastT (B,128,G) ----------------
__global__ void lastT_kernel(const float* __restrict__ emb, const int* __restrict__ last) {
    __shared__ float tile[32][33];
    int b = blockIdx.z;
    int g0 = blockIdx.x * 32, k0 = blockIdx.y * 32;
    int tx = threadIdx.x, ty = threadIdx.y;
#pragma unroll
    for (int i = 0; i < 32; i += 8) {
        int g = g0 + ty + i;
        if (g < Gg) {
            int row = last[b*Gg + g];
            tile[ty+i][tx] = emb[((size_t)b*Nn + row)*Hh + k0 + tx];
        }
    }
    __syncthreads();
#pragma unroll
    for (int i = 0; i < 32; i += 8) {
        int k = k0 + ty + i, g = g0 + tx;
        if (g < Gg) g_lastT[(size_t)b*Hh*Gg + k*Gg + g] = tile[tx][ty+i];
    }
}

// ---------------- q_graph = (colsum/N) @ Wq_graph^T ----------------
__global__ void qgraph_kernel(const float* __restrict__ Wqg) {
    __shared__ float mean_s[128];
    int b = blockIdx.x, t = threadIdx.x;
    mean_s[t] = g_colsum[b*128 + t] * (1.f / (float)Nn);
    __syncthreads();
    float q = 0.f;
#pragma unroll 8
    for (int i = 0; i < 128; ++i) q += mean_s[i] * Wqg[t*128 + i];
    g_qgraph[b*128 + t] = q;
}

// ---------------- GEMM-A: embT^T @ Wall -> K | V | E' (128x128 tiles) ----------------
__global__ __launch_bounds__(256) void gemmA_kernel() {
    extern __shared__ float sm[];
    float* As = sm;            // [128][128]
    float* Bs = sm + 16384;    // [128][128]
    int b = blockIdx.z, c0 = blockIdx.x * 128, n0 = blockIdx.y * 128;
    int tid = threadIdx.x;
    const float* embTb = g_embT + (size_t)b*Hh*Nn;
    load_tile(As, embTb, Nn, n0, Nn, tid);
    // Bs: Wall[k][c0+j], pitch 384, always in-bounds
    for (int s = tid; s < 4096; s += 256) {
        int k = s >> 5, j = (s & 31) * 4;
        *(float4*)(Bs + k*128 + j) = *(const float4*)(g_Wall + k*384 + c0 + j);
    }
    __syncthreads();
    int ty = tid >> 4, tx = tid & 15;
    unsigned long long acc[4][8];
#pragma unroll
    for (int rp = 0; rp < 4; ++rp)
#pragma unroll
        for (int c = 0; c < 8; ++c) acc[rp][c] = 0ull;
    mm_8x8(As, Bs, ty, tx, acc);
    float accf[8][8];
    unpack_acc(acc, accf);

    if (c0 < 256) {
        float* dst = (c0 == 0) ? g_K : g_V;
#pragma unroll
        for (int p = 0; p < 8; ++p) {
            int r = n0 + ty*8 + p;
            if (r >= Nn) continue;
            float* o = dst + ((size_t)b*Nn + r)*Hh + tx*8;
            *(float4*)o       = make_float4(accf[p][0], accf[p][1], accf[p][2], accf[p][3]);
            *(float4*)(o + 4) = make_float4(accf[p][4], accf[p][5], accf[p][6], accf[p][7]);
        }
    } else {
        // stage transposed tile [c][n] in smem, then coalesced copy to EpT
        __syncthreads();
        float* st = sm;  // [128][129]
#pragma unroll
        for (int q = 0; q < 8; ++q)
#pragma unroll
            for (int p = 0; p < 8; ++p)
                st[(tx*8 + q)*129 + ty*8 + p] = accf[p][q];
        __syncthreads();
        float* EpTb = g_EpT + (size_t)b*Hh*Nn;
        for (int s = tid; s < 16384; s += 256) {
            int c = s >> 7, n = s & 127;
            if (n0 + n < Nn) EpTb[(size_t)c*Nn + n0 + n] = st[c*129 + n];
        }
    }
}

// ---------------- GEMM-Q: lastT^T @ WqT + q_graph -> Q (B,G,128) ----------------
__global__ __launch_bounds__(256) void gemmQ_kernel() {
    extern __shared__ float sm[];
    float* As = sm;
    float* Bs = sm + 16384;
    int b = blockIdx.y, g0 = blockIdx.x * 128;
    int tid = threadIdx.x;
    const float* lastTb = g_lastT + (size_t)b*Hh*Gg;
    load_tile(As, lastTb, Gg, g0, Gg, tid);
    for (int s = tid; s < 4096; s += 256) {
        int k = s >> 5, j = (s & 31) * 4;
        *(float4*)(Bs + k*128 + j) = *(const float4*)(g_WqT + k*128 + j);
    }
    __syncthreads();
    int ty = tid >> 4, tx = tid & 15;
    unsigned long long acc[4][8];
#pragma unroll
    for (int rp = 0; rp < 4; ++rp)
#pragma unroll
        for (int c = 0; c < 8; ++c) acc[rp][c] = 0ull;
    mm_8x8(As, Bs, ty, tx, acc);
    float accf[8][8];
    unpack_acc(acc, accf);

    float4 qg0 = *(const float4*)(g_qgraph + b*128 + tx*8);
    float4 qg1 = *(const float4*)(g_qgraph + b*128 + tx*8 + 4);
#pragma unroll
    for (int p = 0; p < 8; ++p) {
        int r = g0 + ty*8 + p;
        if (r >= Gg) continue;
        float* o = g_Q + ((size_t)b*Gg + r)*Hh + tx*8;
        *(float4*)o       = make_float4(accf[p][0]+qg0.x, accf[p][1]+qg0.y, accf[p][2]+qg0.z, accf[p][3]+qg0.w);
        *(float4*)(o + 4) = make_float4(accf[p][4]+qg1.x, accf[p][5]+qg1.y, accf[p][6]+qg1.z, accf[p][7]+qg1.w);
    }
}

// ---------------- glimpse: top-16 neighbors + sparse attention ----------------
__global__ __launch_bounds__(128) void glimpse_kernel(const float* __restrict__ coords,
                                                      const float* __restrict__ mask,
                                                      const int* __restrict__ last) {
    __shared__ float ds[512];
    __shared__ unsigned long long red[4];
    __shared__ int   sel[KNB];
    __shared__ float vsh[KNB*128];
    __shared__ float ssc[128];
    __shared__ float wsh[128];
    int g = blockIdx.x, b = blockIdx.y;
    int tid = threadIdx.x;

    int idxLast = last[b*Gg + g];
    float lx = coords[((size_t)b*Nn + idxLast)*2 + 0];
    float ly = coords[((size_t)b*Nn + idxLast)*2 + 1];

    for (int n = tid; n < 512; n += 128) {
        float d;
        if (n < Nn) {
            float m = mask[((size_t)b*Gg + g)*Nn + n];
            if (m == -INFINITY) d = INFINITY;
            else {
                float dx = lx - coords[((size_t)b*Nn + n)*2 + 0];
                float dy = ly - coords[((size_t)b*Nn + n)*2 + 1];
                d = sqrtf(dx*dx + dy*dy);
            }
        } else d = INFINITY;
        ds[n] = d;
    }
    __syncthreads();

    for (int it = 0; it < KNB; ++it) {
        unsigned long long best = ~0ull;
        for (int n = tid; n < 512; n += 128) {
            unsigned long long key = ((unsigned long long)__float_as_uint(ds[n]) << 32) | (unsigned)n;
            best = min(best, key);
        }
        for (int off = 16; off; off >>= 1)
            best = min(best, __shfl_xor_sync(0xffffffffu, best, off));
        if ((tid & 31) == 0) red[tid >> 5] = best;
        __syncthreads();
        if (tid == 0) {
            unsigned long long m = min(min(red[0], red[1]), min(red[2], red[3]));
            int n = (int)(m & 0xffffffffu);
            sel[it] = n;
            ds[n] = INFINITY;
        }
        __syncthreads();
    }

    float q = g_Q[((size_t)b*Gg + g)*Hh + tid];
#pragma unroll
    for (int j = 0; j < KNB; ++j) {
        int n = sel[j];
        size_t base = ((size_t)b*Nn + n)*Hh;
        float kv = g_K[base + tid];
        vsh[j*128 + tid] = g_V[base + tid];
        float p = q * kv;
        p += __shfl_xor_sync(0xffffffffu, p, 8, 16);
        p += __shfl_xor_sync(0xffffffffu, p, 4, 16);
        p += __shfl_xor_sync(0xffffffffu, p, 2, 16);
        p += __shfl_xor_sync(0xffffffffu, p, 1, 16);
        if ((tid & 15) == 0) ssc[(tid >> 4)*16 + j] = p * 0.25f;
    }
    __syncthreads();

    if (tid < 8) {
        float mx = -INFINITY;
#pragma unroll
        for (int j = 0; j < KNB; ++j) mx = fmaxf(mx, ssc[tid*16 + j]);
        float s = 0.f;
#pragma unroll
        for (int j = 0; j < KNB; ++j) { float e = __expf(ssc[tid*16 + j] - mx); wsh[tid*16 + j] = e; s += e; }
        float inv = 1.f / s;
#pragma unroll
        for (int j = 0; j < KNB; ++j) wsh[tid*16 + j] *= inv;
    }
    __syncthreads();

    int h = tid >> 4;
    float o = 0.f;
#pragma unroll
    for (int j = 0; j < KNB; ++j) o += wsh[h*16 + j] * vsh[j*128 + tid];
    g_attnT[(size_t)b*Hh*Gg + tid*Gg + g] = o;
}

// ---------------- F1: pointer GEMM + tanh + mask -> scores in out ----------------
__global__ __launch_bounds__(256) void final_gemm_kernel(const float* __restrict__ mask,
                                                         float* __restrict__ out) {
    extern __shared__ float sm[];
    float* As = sm;            // attnT tile [128 k][128 g]
    float* Bs = sm + 16384;    // EpT tile   [128 k][128 n]
    int b = blockIdx.z, n0 = blockIdx.x * 128, g0 = blockIdx.y * 128;
    int tid = threadIdx.x;
    load_tile(As, g_attnT + (size_t)b*Hh*Gg, Gg, g0, Gg, tid);
    load_tile(Bs, g_EpT   + (size_t)b*Hh*Nn, Nn, n0, Nn, tid);
    __syncthreads();
    int ty = tid >> 4, tx = tid & 15;
    unsigned long long acc[4][8];
#pragma unroll
    for (int rp = 0; rp < 4; ++rp)
#pragma unroll
        for (int c = 0; c < 8; ++c) acc[rp][c] = 0ull;
    mm_8x8(As, Bs, ty, tx, acc);
    float accf[8][8];
    unpack_acc(acc, accf);

    // biasE for this thread's 8 columns
    float be[8];
#pragma unroll
    for (int q = 0; q < 8; ++q) {
        int n = n0 + tx*8 + q;
        be[q] = (n < Nn) ? g_biasE[b*Nn + n] : 0.f;
    }
#pragma unroll
    for (int p = 0; p < 8; ++p) {
        int g = g0 + ty*8 + p;
        if (g >= Gg) continue;
        const float* mrow = mask + ((size_t)b*Gg + g)*Nn;
        float* orow = out + ((size_t)b*Gg + g)*Nn;
#pragma unroll
        for (int q = 0; q < 8; ++q) {
            int n = n0 + tx*8 + q;
            if (n >= Nn) continue;
            float s = accf[p][q] + be[q];
            orow[n] = tanhf(s) * 10.0f + mrow[n];
        }
    }
}

// ---------------- F2: warp-per-row softmax, in place on out ----------------
__global__ __launch_bounds__(256) void softmax_kernel(float* __restrict__ out) {
    int warp = threadIdx.x >> 5, lane = threadIdx.x & 31;
    int r = blockIdx.x * 8 + warp;
    if (r >= Bsz*Gg) return;
    float* row = out + (size_t)r*Nn;
    float v[16];
    float m = -INFINITY;
#pragma unroll
    for (int i = 0; i < 16; ++i) {
        int n = lane + i*32;
        v[i] = (n < Nn) ? row[n] : -INFINITY;
        m = fmaxf(m, v[i]);
    }
    for (int off = 16; off; off >>= 1) m = fmaxf(m, __shfl_xor_sync(0xffffffffu, m, off));
    float s = 0.f;
#pragma unroll
    for (int i = 0; i < 16; ++i) { float e = __expf(v[i] - m); v[i] = e; s += e; }
    for (int off = 16; off; off >>= 1) s += __shfl_xor_sync(0xffffffffu, s, off);
    float inv = 1.f / s;
#pragma unroll
    for (int i = 0; i < 16; ++i) {
        int n = lane + i*32;
        if (n < Nn) row[n] = v[i] * inv;
    }
}

// ---------------- host ----------------
extern "C" void kernel_launch(void* const* d_in, const int* in_sizes, int n_in,
                              void* d_out, int out_size) {
    const float* coords   = (const float*)d_in[0];
    const float* emb      = (const float*)d_in[1];
    const int*   last     = (const int*)  d_in[2];
    const float* mask     = (const float*)d_in[3];
    const float* Wq_graph = (const float*)d_in[4];
    const float* Wq_first = (const float*)d_in[5];
    const float* Wq_last  = (const float*)d_in[6];
    const float* Wk       = (const float*)d_in[7];
    const float* Wv       = (const float*)d_in[8];
    const float* Wc       = (const float*)d_in[9];
    const float* bc       = (const float*)d_in[10];
    float* out = (float*)d_out;

    cudaFuncSetAttribute(gemmA_kernel,      cudaFuncAttributeMaxDynamicSharedMemorySize, 131072);
    cudaFuncSetAttribute(gemmQ_kernel,      cudaFuncAttributeMaxDynamicSharedMemorySize, 131072);
    cudaFuncSetAttribute(final_gemm_kernel, cudaFuncAttributeMaxDynamicSharedMemorySize, 131072);

    wprep_kernel<<<256, 256>>>(Wk, Wv, Wc, Wq_first, Wq_last);
    embT_kernel<<<dim3(16, 4, Bsz), dim3(32, 8)>>>(emb, bc);
    lastT_kernel<<<dim3(16, 4, Bsz), dim3(32, 8)>>>(emb, last);
    qgraph_kernel<<<Bsz, 128>>>(Wq_graph);
    gemmA_kernel<<<dim3(3, 4, Bsz), 256, 131072>>>();
    gemmQ_kernel<<<dim3(4, Bsz), 256, 131072>>>();
    glimpse_kernel<<<dim3(Gg, Bsz), 128>>>(coords, mask, last);
    final_gemm_kernel<<<dim3(4, 4, Bsz), 256, 131072>>>(mask, out);
    softmax_kernel<<<2000, 256>>>(out);
}

// round 8
// speedup vs baseline: 1.5587x; 1.2293x over previous
#include <cuda_runtime.h>
#include <math.h>
#include <stdint.h>

#define Bsz 32
#define Nn  500
#define Gg  500
#define Hh  128
#define KNB 16

// ---------------- scratch (device globals; no allocation) ----------------
__device__ float g_colsum[Bsz*Hh];
__device__ float g_Wall[Hh*384];             // [k][j]: j<128 Wk^T, <256 Wv^T, <384 Wc
__device__ float g_WqT[Hh*Hh];               // [k][o] = Wq_first[o][k]+Wq_last[o][k]
__device__ float g_embT[Bsz*Hh*Nn];          // (B,128,N)  k-major embeddings
__device__ float g_lastT[Bsz*Hh*Gg];         // (B,128,G)  k-major gathered last_emb
__device__ float g_K[(size_t)Bsz*Nn*Hh];     // (B,N,128)
__device__ float g_V[(size_t)Bsz*Nn*Hh];     // (B,N,128)
__device__ float g_EpT[Bsz*Hh*Nn];           // (B,128,N)  E' = emb@Wc, k-major
__device__ float g_biasE[Bsz*Nn];            // bc . emb[b,n]
__device__ float g_Q[(size_t)Bsz*Gg*Hh];     // (B,G,128)
__device__ float g_attnT[Bsz*Hh*Gg];         // (B,128,G)  attention out, k-major

// ---------------- f32x2 packed-FMA fabric ----------------
__device__ __forceinline__ void ffma2(unsigned long long &d, unsigned long long a, unsigned long long b) {
    asm("fma.rn.f32x2 %0, %1, %2, %0;" : "+l"(d) : "l"(a), "l"(b));
}
__device__ __forceinline__ unsigned long long bpack(float x) {
    unsigned long long r;
    asm("mov.b64 %0, {%1, %1};" : "=l"(r) : "f"(x));
    return r;
}
__device__ __forceinline__ void unpack2(unsigned long long v, float &lo, float &hi) {
    asm("mov.b64 {%0, %1}, %2;" : "=f"(lo), "=f"(hi) : "l"(v));
}

// 64-k chunk of the 8x8 micro-tile mainloop. As/Bs: [64][128].
__device__ __forceinline__ void mm64(const float* __restrict__ As, const float* __restrict__ Bs,
                                     int ty, int tx, unsigned long long acc[4][8]) {
#pragma unroll 8
    for (int k = 0; k < 64; ++k) {
        ulonglong2 aA = *(const ulonglong2*)(As + k*128 + ty*8);
        ulonglong2 aB = *(const ulonglong2*)(As + k*128 + ty*8 + 4);
        float4 b0 = *(const float4*)(Bs + k*128 + tx*8);
        float4 b1 = *(const float4*)(Bs + k*128 + tx*8 + 4);
        unsigned long long bb[8];
        bb[0]=bpack(b0.x); bb[1]=bpack(b0.y); bb[2]=bpack(b0.z); bb[3]=bpack(b0.w);
        bb[4]=bpack(b1.x); bb[5]=bpack(b1.y); bb[6]=bpack(b1.z); bb[7]=bpack(b1.w);
#pragma unroll
        for (int c = 0; c < 8; ++c) {
            ffma2(acc[0][c], aA.x, bb[c]);
            ffma2(acc[1][c], aA.y, bb[c]);
            ffma2(acc[2][c], aB.x, bb[c]);
            ffma2(acc[3][c], aB.y, bb[c]);
        }
    }
}
__device__ __forceinline__ void unpack_acc(unsigned long long acc[4][8], float accf[8][8]) {
#pragma unroll
    for (int rp = 0; rp < 4; ++rp)
#pragma unroll
        for (int c = 0; c < 8; ++c)
            unpack2(acc[rp][c], accf[2*rp][c], accf[2*rp+1][c]);
}

// fill one [64][128] k-chunk from k-major src (row pitch), cols j0.., guard jmax
__device__ __forceinline__ void fill_k(float* __restrict__ dst, const float* __restrict__ src,
                                       int pitch, int j0, int jmax, int kc, int tid) {
#pragma unroll
    for (int it = 0; it < 8; ++it) {
        int idx = tid + it*256;          // 2048 float4 slots
        int k = idx >> 5, jq = idx & 31;
        int j = j0 + jq*4;
        const float* p = src + (size_t)(kc*64 + k)*pitch + j;
        float4 v;
        if (j + 3 < jmax) v = *(const float4*)p;
        else {
            v.x = (j   < jmax) ? p[0] : 0.f;
            v.y = (j+1 < jmax) ? p[1] : 0.f;
            v.z = (j+2 < jmax) ? p[2] : 0.f;
            v.w = (j+3 < jmax) ? p[3] : 0.f;
        }
        *(float4*)(dst + k*128 + jq*4) = v;
    }
}

// fast tanh: (1 - e) * rcp(1 + e), e = exp(-2|x|); err ~1e-7
__device__ __forceinline__ float fast_tanh(float x) {
    float a = fabsf(x);
    float e = __expf(-2.f * a);
    float t = __fdividef(1.f - e, 1.f + e);
    return copysignf(t, x);
}

// ---------------- prep1: weight transposes + zero colsum/biasE ----------------
__global__ void prep1_kernel(const float* __restrict__ Wk, const float* __restrict__ Wv,
                             const float* __restrict__ Wc, const float* __restrict__ Wqf,
                             const float* __restrict__ Wql) {
    int idx = blockIdx.x * blockDim.x + threadIdx.x;
    const int total1 = Hh * 384;
    if (idx < total1) {
        int k = idx / 384, j = idx % 384;
        float v;
        if (j < 128)      v = Wk[j*128 + k];
        else if (j < 256) v = Wv[(j-128)*128 + k];
        else              v = Wc[k*128 + (j-256)];
        g_Wall[idx] = v;
    }
    int idx2 = idx - total1;
    if (idx2 >= 0 && idx2 < Hh*Hh) {
        int k = idx2 / 128, o = idx2 % 128;
        g_WqT[idx2] = Wqf[o*128 + k] + Wql[o*128 + k];
    }
    if (idx < Bsz*Hh) g_colsum[idx] = 0.f;
    if (idx < Bsz*Nn) g_biasE[idx] = 0.f;
}

// ---------------- prep2: embT(+colsum+biasE) and lastT, merged ----------------
__global__ void prep2_kernel(const float* __restrict__ emb, const float* __restrict__ bc,
                             const int* __restrict__ last) {
    __shared__ float tile[32][33];
    int tid = threadIdx.x;
    int tx = tid & 31, ty = tid >> 5;
    int bid = blockIdx.x;
    if (bid < 2048) {
        int b = bid >> 6, k0 = ((bid >> 4) & 3) * 32, n0 = (bid & 15) * 32;
        float bcv = bc[k0 + tx];
        float csum = 0.f;
#pragma unroll
        for (int i = 0; i < 32; i += 8) {
            int n = n0 + ty + i;
            float v = 0.f;
            if (n < Nn) { v = emb[((size_t)b*Nn + n)*Hh + k0 + tx]; tile[ty+i][tx] = v; }
            csum += v;
            float contrib = v * bcv;
            for (int off = 16; off; off >>= 1)
                contrib += __shfl_xor_sync(0xffffffffu, contrib, off);
            if (tx == 0 && n < Nn) atomicAdd(&g_biasE[b*Nn + n], contrib);
        }
        atomicAdd(&g_colsum[b*128 + k0 + tx], csum);
        __syncthreads();
#pragma unroll
        for (int i = 0; i < 32; i += 8) {
            int k = k0 + ty + i, n = n0 + tx;
            if (n < Nn) g_embT[(size_t)b*Hh*Nn + k*Nn + n] = tile[tx][ty+i];
        }
    } else {
        int e = bid - 2048;
        int b = e >> 6, k0 = ((e >> 4) & 3) * 32, g0 = (e & 15) * 32;
#pragma unroll
        for (int i = 0; i < 32; i += 8) {
            int g = g0 + ty + i;
            if (g < Gg) {
                int row = last[b*Gg + g];
                tile[ty+i][tx] = emb[((size_t)b*Nn + row)*Hh + k0 + tx];
            }
        }
        __syncthreads();
#pragma unroll
        for (int i = 0; i < 32; i += 8) {
            int k = k0 + ty + i, g = g0 + tx;
            if (g < Gg) g_lastT[(size_t)b*Hh*Gg + k*Gg + g] = tile[tx][ty+i];
        }
    }
}

// ---------------- gemms: A-path (K|V|E') and Q-path (+q_graph), merged ----------------
// dyn smem: As [64][128] + Bs [64][128] = 65536 B; E' staging reuses 66048 B.
__global__ __launch_bounds__(256, 2) void gemms_kernel(const float* __restrict__ Wqg) {
    extern __shared__ float sm[];
    float* As = sm;
    float* Bs = sm + 8192;
    __shared__ float mean_s[128];
    __shared__ float qg_s[128];
    int tid = threadIdx.x;
    int bid = blockIdx.x;
    int ty = tid >> 4, tx = tid & 15;
    unsigned long long acc[4][8];
#pragma unroll
    for (int rp = 0; rp < 4; ++rp)
#pragma unroll
        for (int c = 0; c < 8; ++c) acc[rp][c] = 0ull;

    if (bid < 384) {
        // ---- GEMM-A: out cols c0 (0:K,128:V,256:E'), rows n0 ----
        int c = bid % 3, nt = (bid / 3) % 4, b = bid / 12;
        int c0 = c * 128, n0 = nt * 128;
        const float* embTb = g_embT + (size_t)b*Hh*Nn;
#pragma unroll
        for (int kc = 0; kc < 2; ++kc) {
            fill_k(As, embTb, Nn, n0, Nn, kc, tid);
            fill_k(Bs, g_Wall, 384, c0, 1 << 30, kc, tid);
            __syncthreads();
            mm64(As, Bs, ty, tx, acc);
            __syncthreads();
        }
        float accf[8][8];
        unpack_acc(acc, accf);
        if (c0 < 256) {
            float* dst = (c0 == 0) ? g_K : g_V;
#pragma unroll
            for (int p = 0; p < 8; ++p) {
                int r = n0 + ty*8 + p;
                if (r >= Nn) continue;
                float* o = dst + ((size_t)b*Nn + r)*Hh + tx*8;
                *(float4*)o       = make_float4(accf[p][0], accf[p][1], accf[p][2], accf[p][3]);
                *(float4*)(o + 4) = make_float4(accf[p][4], accf[p][5], accf[p][6], accf[p][7]);
            }
        } else {
            // stage transposed [c][n] then coalesced copy to EpT
            float* st = sm;  // [128][129]
#pragma unroll
            for (int q = 0; q < 8; ++q)
#pragma unroll
                for (int p = 0; p < 8; ++p)
                    st[(tx*8 + q)*129 + ty*8 + p] = accf[p][q];
            __syncthreads();
            float* EpTb = g_EpT + (size_t)b*Hh*Nn;
            for (int s = tid; s < 16384; s += 256) {
                int cc = s >> 7, n = s & 127;
                if (n0 + n < Nn) EpTb[(size_t)cc*Nn + n0 + n] = st[cc*129 + n];
            }
        }
    } else {
        // ---- GEMM-Q (+ inline q_graph) ----
        int q = bid - 384;
        int gt = q % 4, b = q / 4;
        int g0 = gt * 128;
        if (tid < 128) mean_s[tid] = g_colsum[b*128 + tid] * (1.f / (float)Nn);
        __syncthreads();
        {   // q_graph: 8 warps x 16 outputs, coalesced Wqg rows
            int w = tid >> 5, lane = tid & 31;
            for (int o = w*16; o < w*16 + 16; ++o) {
                float s = 0.f;
#pragma unroll
                for (int i = lane; i < 128; i += 32) s += mean_s[i] * Wqg[o*128 + i];
                for (int off = 16; off; off >>= 1) s += __shfl_xor_sync(0xffffffffu, s, off);
                if (lane == 0) qg_s[o] = s;
            }
        }
        const float* lastTb = g_lastT + (size_t)b*Hh*Gg;
#pragma unroll
        for (int kc = 0; kc < 2; ++kc) {
            fill_k(As, lastTb, Gg, g0, Gg, kc, tid);
            fill_k(Bs, g_WqT, 128, 0, 1 << 30, kc, tid);
            __syncthreads();
            mm64(As, Bs, ty, tx, acc);
            __syncthreads();
        }
        float accf[8][8];
        unpack_acc(acc, accf);
        float4 qg0 = *(const float4*)(qg_s + tx*8);
        float4 qg1 = *(const float4*)(qg_s + tx*8 + 4);
#pragma unroll
        for (int p = 0; p < 8; ++p) {
            int r = g0 + ty*8 + p;
            if (r >= Gg) continue;
            float* o = g_Q + ((size_t)b*Gg + r)*Hh + tx*8;
            *(float4*)o       = make_float4(accf[p][0]+qg0.x, accf[p][1]+qg0.y, accf[p][2]+qg0.z, accf[p][3]+qg0.w);
            *(float4*)(o + 4) = make_float4(accf[p][4]+qg1.x, accf[p][5]+qg1.y, accf[p][6]+qg1.z, accf[p][7]+qg1.w);
        }
    }
}

// ---------------- glimpse: top-16 neighbors + sparse attention ----------------
__global__ __launch_bounds__(128) void glimpse_kernel(const float* __restrict__ coords,
                                                      const float* __restrict__ mask,
                                                      const int* __restrict__ last) {
    __shared__ float ds[512];
    __shared__ unsigned long long red[4];
    __shared__ int   sel[KNB];
    __shared__ float vsh[KNB*128];
    __shared__ float ssc[128];
    __shared__ float wsh[128];
    int g = blockIdx.x, b = blockIdx.y;
    int tid = threadIdx.x;

    int idxLast = last[b*Gg + g];
    float lx = coords[((size_t)b*Nn + idxLast)*2 + 0];
    float ly = coords[((size_t)b*Nn + idxLast)*2 + 1];

    for (int n = tid; n < 512; n += 128) {
        float d;
        if (n < Nn) {
            float m = mask[((size_t)b*Gg + g)*Nn + n];
            if (m == -INFINITY) d = INFINITY;
            else {
                float dx = lx - coords[((size_t)b*Nn + n)*2 + 0];
                float dy = ly - coords[((size_t)b*Nn + n)*2 + 1];
                d = sqrtf(dx*dx + dy*dy);
            }
        } else d = INFINITY;
        ds[n] = d;
    }
    __syncthreads();

    for (int it = 0; it < KNB; ++it) {
        unsigned long long best = ~0ull;
        for (int n = tid; n < 512; n += 128) {
            unsigned long long key = ((unsigned long long)__float_as_uint(ds[n]) << 32) | (unsigned)n;
            best = min(best, key);
        }
        for (int off = 16; off; off >>= 1)
            best = min(best, __shfl_xor_sync(0xffffffffu, best, off));
        if ((tid & 31) == 0) red[tid >> 5] = best;
        __syncthreads();
        if (tid == 0) {
            unsigned long long m = min(min(red[0], red[1]), min(red[2], red[3]));
            int n = (int)(m & 0xffffffffu);
            sel[it] = n;
            ds[n] = INFINITY;
        }
        __syncthreads();
    }

    float qv = g_Q[((size_t)b*Gg + g)*Hh + tid];
#pragma unroll
    for (int j = 0; j < KNB; ++j) {
        int n = sel[j];
        size_t base = ((size_t)b*Nn + n)*Hh;
        float kv = g_K[base + tid];
        vsh[j*128 + tid] = g_V[base + tid];
        float p = qv * kv;
        p += __shfl_xor_sync(0xffffffffu, p, 8, 16);
        p += __shfl_xor_sync(0xffffffffu, p, 4, 16);
        p += __shfl_xor_sync(0xffffffffu, p, 2, 16);
        p += __shfl_xor_sync(0xffffffffu, p, 1, 16);
        if ((tid & 15) == 0) ssc[(tid >> 4)*16 + j] = p * 0.25f;
    }
    __syncthreads();

    if (tid < 8) {
        float mx = -INFINITY;
#pragma unroll
        for (int j = 0; j < KNB; ++j) mx = fmaxf(mx, ssc[tid*16 + j]);
        float s = 0.f;
#pragma unroll
        for (int j = 0; j < KNB; ++j) { float e = __expf(ssc[tid*16 + j] - mx); wsh[tid*16 + j] = e; s += e; }
        float inv = 1.f / s;
#pragma unroll
        for (int j = 0; j < KNB; ++j) wsh[tid*16 + j] *= inv;
    }
    __syncthreads();

    int h = tid >> 4;
    float o = 0.f;
#pragma unroll
    for (int j = 0; j < KNB; ++j) o += wsh[h*16 + j] * vsh[j*128 + tid];
    g_attnT[(size_t)b*Hh*Gg + tid*Gg + g] = o;
}

// ---------------- F1: pointer GEMM + tanh + mask -> scores in out ----------------
__global__ __launch_bounds__(256, 2) void final_gemm_kernel(const float* __restrict__ mask,
                                                            float* __restrict__ out) {
    extern __shared__ float sm[];
    float* As = sm;          // attnT chunk [64][128 g]
    float* Bs = sm + 8192;   // EpT  chunk [64][128 n]
    int b = blockIdx.z, n0 = blockIdx.x * 128, g0 = blockIdx.y * 128;
    int tid = threadIdx.x;
    int ty = tid >> 4, tx = tid & 15;
    unsigned long long acc[4][8];
#pragma unroll
    for (int rp = 0; rp < 4; ++rp)
#pragma unroll
        for (int c = 0; c < 8; ++c) acc[rp][c] = 0ull;

    const float* attnTb = g_attnT + (size_t)b*Hh*Gg;
    const float* EpTb   = g_EpT   + (size_t)b*Hh*Nn;
#pragma unroll
    for (int kc = 0; kc < 2; ++kc) {
        fill_k(As, attnTb, Gg, g0, Gg, kc, tid);
        fill_k(Bs, EpTb,   Nn, n0, Nn, kc, tid);
        __syncthreads();
        mm64(As, Bs, ty, tx, acc);
        __syncthreads();
    }
    float accf[8][8];
    unpack_acc(acc, accf);

    float be[8];
#pragma unroll
    for (int q = 0; q < 8; ++q) {
        int n = n0 + tx*8 + q;
        be[q] = (n < Nn) ? g_biasE[b*Nn + n] : 0.f;
    }
#pragma unroll
    for (int p = 0; p < 8; ++p) {
        int g = g0 + ty*8 + p;
        if (g >= Gg) continue;
        const float* mrow = mask + ((size_t)b*Gg + g)*Nn;
        float* orow = out + ((size_t)b*Gg + g)*Nn;
#pragma unroll
        for (int q = 0; q < 8; ++q) {
            int n = n0 + tx*8 + q;
            if (n >= Nn) continue;
            float s = accf[p][q] + be[q];
            orow[n] = fast_tanh(s) * 10.0f + mrow[n];
        }
    }
}

// ---------------- F2: warp-per-row softmax, in place on out ----------------
__global__ __launch_bounds__(256) void softmax_kernel(float* __restrict__ out) {
    int warp = threadIdx.x >> 5, lane = threadIdx.x & 31;
    int r = blockIdx.x * 8 + warp;
    if (r >= Bsz*Gg) return;
    float* row = out + (size_t)r*Nn;
    float v[16];
    float m = -INFINITY;
#pragma unroll
    for (int i = 0; i < 16; ++i) {
        int n = lane + i*32;
        v[i] = (n < Nn) ? row[n] : -INFINITY;
        m = fmaxf(m, v[i]);
    }
    for (int off = 16; off; off >>= 1) m = fmaxf(m, __shfl_xor_sync(0xffffffffu, m, off));
    float s = 0.f;
#pragma unroll
    for (int i = 0; i < 16; ++i) { float e = __expf(v[i] - m); v[i] = e; s += e; }
    for (int off = 16; off; off >>= 1) s += __shfl_xor_sync(0xffffffffu, s, off);
    float inv = 1.f / s;
#pragma unroll
    for (int i = 0; i < 16; ++i) {
        int n = lane + i*32;
        if (n < Nn) row[n] = v[i] * inv;
    }
}

// ---------------- host ----------------
extern "C" void kernel_launch(void* const* d_in, const int* in_sizes, int n_in,
                              void* d_out, int out_size) {
    const float* coords   = (const float*)d_in[0];
    const float* emb      = (const float*)d_in[1];
    const int*   last     = (const int*)  d_in[2];
    const float* mask     = (const float*)d_in[3];
    const float* Wq_graph = (const float*)d_in[4];
    const float* Wq_first = (const float*)d_in[5];
    const float* Wq_last  = (const float*)d_in[6];
    const float* Wk       = (const float*)d_in[7];
    const float* Wv       = (const float*)d_in[8];
    const float* Wc       = (const float*)d_in[9];
    const float* bc       = (const float*)d_in[10];
    float* out = (float*)d_out;

    cudaFuncSetAttribute(gemms_kernel,      cudaFuncAttributeMaxDynamicSharedMemorySize, 66048);
    cudaFuncSetAttribute(final_gemm_kernel, cudaFuncAttributeMaxDynamicSharedMemorySize, 65536);

    prep1_kernel<<<256, 256>>>(Wk, Wv, Wc, Wq_first, Wq_last);
    prep2_kernel<<<4096, 256>>>(emb, bc, last);
    gemms_kernel<<<512, 256, 66048>>>(Wq_graph);
    glimpse_kernel<<<dim3(Gg, Bsz), 128>>>(coords, mask, last);
    final_gemm_kernel<<<dim3(4, 4, Bsz), 256, 65536>>>(mask, out);
    softmax_kernel<<<2000, 256>>>(out);
}

// round 9
// speedup vs baseline: 1.8405x; 1.1809x over previous
#include <cuda_runtime.h>
#include <math.h>
#include <stdint.h>

#define Bsz 32
#define Nn  500
#define Gg  500
#define Hh  128
#define KNB 16

// ---------------- scratch (device globals; no allocation) ----------------
__device__ float g_colsum[Bsz*Hh];
__device__ float g_Wall[Hh*384];             // [k][j]: j<128 Wk^T, <256 Wv^T, <384 Wc
__device__ float g_WqT[Hh*Hh];               // [k][o] = Wq_first[o][k]+Wq_last[o][k]
__device__ float g_embT[Bsz*Hh*Nn];          // (B,128,N)  k-major embeddings
__device__ float g_lastT[Bsz*Hh*Gg];         // (B,128,G)  k-major gathered last_emb
__device__ float g_K[(size_t)Bsz*Nn*Hh];     // (B,N,128)
__device__ float g_V[(size_t)Bsz*Nn*Hh];     // (B,N,128)
__device__ float g_EpT[Bsz*Hh*Nn];           // (B,128,N)  E' = emb@Wc, k-major
__device__ float g_biasE[Bsz*Nn];            // bc . emb[b,n]
__device__ float g_Q[(size_t)Bsz*Gg*Hh];     // (B,G,128)
__device__ float g_attnT[Bsz*Hh*Gg];         // (B,128,G)  attention out, k-major

// ---------------- f32x2 packed-FMA fabric ----------------
__device__ __forceinline__ void ffma2(unsigned long long &d, unsigned long long a, unsigned long long b) {
    asm("fma.rn.f32x2 %0, %1, %2, %0;" : "+l"(d) : "l"(a), "l"(b));
}
__device__ __forceinline__ unsigned long long bpack(float x) {
    unsigned long long r;
    asm("mov.b64 %0, {%1, %1};" : "=l"(r) : "f"(x));
    return r;
}
__device__ __forceinline__ void unpack2(unsigned long long v, float &lo, float &hi) {
    asm("mov.b64 {%0, %1}, %2;" : "=f"(lo), "=f"(hi) : "l"(v));
}

// 64-k chunk of the 8x8 micro-tile mainloop. As/Bs: [64][128].
__device__ __forceinline__ void mm64(const float* __restrict__ As, const float* __restrict__ Bs,
                                     int ty, int tx, unsigned long long acc[4][8]) {
#pragma unroll 8
    for (int k = 0; k < 64; ++k) {
        ulonglong2 aA = *(const ulonglong2*)(As + k*128 + ty*8);
        ulonglong2 aB = *(const ulonglong2*)(As + k*128 + ty*8 + 4);
        float4 b0 = *(const float4*)(Bs + k*128 + tx*8);
        float4 b1 = *(const float4*)(Bs + k*128 + tx*8 + 4);
        unsigned long long bb[8];
        bb[0]=bpack(b0.x); bb[1]=bpack(b0.y); bb[2]=bpack(b0.z); bb[3]=bpack(b0.w);
        bb[4]=bpack(b1.x); bb[5]=bpack(b1.y); bb[6]=bpack(b1.z); bb[7]=bpack(b1.w);
#pragma unroll
        for (int c = 0; c < 8; ++c) {
            ffma2(acc[0][c], aA.x, bb[c]);
            ffma2(acc[1][c], aA.y, bb[c]);
            ffma2(acc[2][c], aB.x, bb[c]);
            ffma2(acc[3][c], aB.y, bb[c]);
        }
    }
}
__device__ __forceinline__ void unpack_acc(unsigned long long acc[4][8], float accf[8][8]) {
#pragma unroll
    for (int rp = 0; rp < 4; ++rp)
#pragma unroll
        for (int c = 0; c < 8; ++c)
            unpack2(acc[rp][c], accf[2*rp][c], accf[2*rp+1][c]);
}

// fill one [64][128] k-chunk from k-major src (row pitch), cols j0.., guard jmax
__device__ __forceinline__ void fill_k(float* __restrict__ dst, const float* __restrict__ src,
                                       int pitch, int j0, int jmax, int kc, int tid) {
#pragma unroll
    for (int it = 0; it < 8; ++it) {
        int idx = tid + it*256;          // 2048 float4 slots
        int k = idx >> 5, jq = idx & 31;
        int j = j0 + jq*4;
        const float* p = src + (size_t)(kc*64 + k)*pitch + j;
        float4 v;
        if (j + 3 < jmax) v = *(const float4*)p;
        else {
            v.x = (j   < jmax) ? p[0] : 0.f;
            v.y = (j+1 < jmax) ? p[1] : 0.f;
            v.z = (j+2 < jmax) ? p[2] : 0.f;
            v.w = (j+3 < jmax) ? p[3] : 0.f;
        }
        *(float4*)(dst + k*128 + jq*4) = v;
    }
}

// fast tanh: (1 - e) * rcp(1 + e), e = exp(-2|x|); err ~1e-7
__device__ __forceinline__ float fast_tanh(float x) {
    float a = fabsf(x);
    float e = __expf(-2.f * a);
    float t = __fdividef(1.f - e, 1.f + e);
    return copysignf(t, x);
}

// ---------------- prep1: weight transposes + zero colsum/biasE ----------------
__global__ void prep1_kernel(const float* __restrict__ Wk, const float* __restrict__ Wv,
                             const float* __restrict__ Wc, const float* __restrict__ Wqf,
                             const float* __restrict__ Wql) {
    int idx = blockIdx.x * blockDim.x + threadIdx.x;
    const int total1 = Hh * 384;
    if (idx < total1) {
        int k = idx / 384, j = idx % 384;
        float v;
        if (j < 128)      v = Wk[j*128 + k];
        else if (j < 256) v = Wv[(j-128)*128 + k];
        else              v = Wc[k*128 + (j-256)];
        g_Wall[idx] = v;
    }
    int idx2 = idx - total1;
    if (idx2 >= 0 && idx2 < Hh*Hh) {
        int k = idx2 / 128, o = idx2 % 128;
        g_WqT[idx2] = Wqf[o*128 + k] + Wql[o*128 + k];
    }
    if (idx < Bsz*Hh) g_colsum[idx] = 0.f;
    if (idx < Bsz*Nn) g_biasE[idx] = 0.f;
}

// ---------------- prep2: embT(+colsum+biasE) and lastT, merged ----------------
__global__ void prep2_kernel(const float* __restrict__ emb, const float* __restrict__ bc,
                             const int* __restrict__ last) {
    __shared__ float tile[32][33];
    int tid = threadIdx.x;
    int tx = tid & 31, ty = tid >> 5;
    int bid = blockIdx.x;
    if (bid < 2048) {
        int b = bid >> 6, k0 = ((bid >> 4) & 3) * 32, n0 = (bid & 15) * 32;
        float bcv = bc[k0 + tx];
        float csum = 0.f;
#pragma unroll
        for (int i = 0; i < 32; i += 8) {
            int n = n0 + ty + i;
            float v = 0.f;
            if (n < Nn) { v = emb[((size_t)b*Nn + n)*Hh + k0 + tx]; tile[ty+i][tx] = v; }
            csum += v;
            float contrib = v * bcv;
            for (int off = 16; off; off >>= 1)
                contrib += __shfl_xor_sync(0xffffffffu, contrib, off);
            if (tx == 0 && n < Nn) atomicAdd(&g_biasE[b*Nn + n], contrib);
        }
        atomicAdd(&g_colsum[b*128 + k0 + tx], csum);
        __syncthreads();
#pragma unroll
        for (int i = 0; i < 32; i += 8) {
            int k = k0 + ty + i, n = n0 + tx;
            if (n < Nn) g_embT[(size_t)b*Hh*Nn + k*Nn + n] = tile[tx][ty+i];
        }
    } else {
        int e = bid - 2048;
        int b = e >> 6, k0 = ((e >> 4) & 3) * 32, g0 = (e & 15) * 32;
#pragma unroll
        for (int i = 0; i < 32; i += 8) {
            int g = g0 + ty + i;
            if (g < Gg) {
                int row = last[b*Gg + g];
                tile[ty+i][tx] = emb[((size_t)b*Nn + row)*Hh + k0 + tx];
            }
        }
        __syncthreads();
#pragma unroll
        for (int i = 0; i < 32; i += 8) {
            int k = k0 + ty + i, g = g0 + tx;
            if (g < Gg) g_lastT[(size_t)b*Hh*Gg + k*Gg + g] = tile[tx][ty+i];
        }
    }
}

// ---------------- gemms: A-path (K|V|E') and Q-path (+q_graph), merged ----------------
__global__ __launch_bounds__(256, 2) void gemms_kernel(const float* __restrict__ Wqg) {
    extern __shared__ float sm[];
    float* As = sm;
    float* Bs = sm + 8192;
    __shared__ float mean_s[128];
    __shared__ float qg_s[128];
    int tid = threadIdx.x;
    int bid = blockIdx.x;
    int ty = tid >> 4, tx = tid & 15;
    unsigned long long acc[4][8];
#pragma unroll
    for (int rp = 0; rp < 4; ++rp)
#pragma unroll
        for (int c = 0; c < 8; ++c) acc[rp][c] = 0ull;

    if (bid < 384) {
        int c = bid % 3, nt = (bid / 3) % 4, b = bid / 12;
        int c0 = c * 128, n0 = nt * 128;
        const float* embTb = g_embT + (size_t)b*Hh*Nn;
#pragma unroll
        for (int kc = 0; kc < 2; ++kc) {
            fill_k(As, embTb, Nn, n0, Nn, kc, tid);
            fill_k(Bs, g_Wall, 384, c0, 1 << 30, kc, tid);
            __syncthreads();
            mm64(As, Bs, ty, tx, acc);
            __syncthreads();
        }
        float accf[8][8];
        unpack_acc(acc, accf);
        if (c0 < 256) {
            float* dst = (c0 == 0) ? g_K : g_V;
#pragma unroll
            for (int p = 0; p < 8; ++p) {
                int r = n0 + ty*8 + p;
                if (r >= Nn) continue;
                float* o = dst + ((size_t)b*Nn + r)*Hh + tx*8;
                *(float4*)o       = make_float4(accf[p][0], accf[p][1], accf[p][2], accf[p][3]);
                *(float4*)(o + 4) = make_float4(accf[p][4], accf[p][5], accf[p][6], accf[p][7]);
            }
        } else {
            float* st = sm;  // [128][129]
#pragma unroll
            for (int q = 0; q < 8; ++q)
#pragma unroll
                for (int p = 0; p < 8; ++p)
                    st[(tx*8 + q)*129 + ty*8 + p] = accf[p][q];
            __syncthreads();
            float* EpTb = g_EpT + (size_t)b*Hh*Nn;
            for (int s = tid; s < 16384; s += 256) {
                int cc = s >> 7, n = s & 127;
                if (n0 + n < Nn) EpTb[(size_t)cc*Nn + n0 + n] = st[cc*129 + n];
            }
        }
    } else {
        int q = bid - 384;
        int gt = q % 4, b = q / 4;
        int g0 = gt * 128;
        if (tid < 128) mean_s[tid] = g_colsum[b*128 + tid] * (1.f / (float)Nn);
        __syncthreads();
        {
            int w = tid >> 5, lane = tid & 31;
            for (int o = w*16; o < w*16 + 16; ++o) {
                float s = 0.f;
#pragma unroll
                for (int i = lane; i < 128; i += 32) s += mean_s[i] * Wqg[o*128 + i];
                for (int off = 16; off; off >>= 1) s += __shfl_xor_sync(0xffffffffu, s, off);
                if (lane == 0) qg_s[o] = s;
            }
        }
        const float* lastTb = g_lastT + (size_t)b*Hh*Gg;
#pragma unroll
        for (int kc = 0; kc < 2; ++kc) {
            fill_k(As, lastTb, Gg, g0, Gg, kc, tid);
            fill_k(Bs, g_WqT, 128, 0, 1 << 30, kc, tid);
            __syncthreads();
            mm64(As, Bs, ty, tx, acc);
            __syncthreads();
        }
        float accf[8][8];
        unpack_acc(acc, accf);
        float4 qg0 = *(const float4*)(qg_s + tx*8);
        float4 qg1 = *(const float4*)(qg_s + tx*8 + 4);
#pragma unroll
        for (int p = 0; p < 8; ++p) {
            int r = g0 + ty*8 + p;
            if (r >= Gg) continue;
            float* o = g_Q + ((size_t)b*Gg + r)*Hh + tx*8;
            *(float4*)o       = make_float4(accf[p][0]+qg0.x, accf[p][1]+qg0.y, accf[p][2]+qg0.z, accf[p][3]+qg0.w);
            *(float4*)(o + 4) = make_float4(accf[p][4]+qg1.x, accf[p][5]+qg1.y, accf[p][6]+qg1.z, accf[p][7]+qg1.w);
        }
    }
}

// ---------------- glimpse: register-resident warp-local top-16 + sparse attention ----------------
__device__ __forceinline__ void cswap(unsigned long long &a, unsigned long long &b) {
    unsigned long long lo = min(a, b), hi = max(a, b);
    a = lo; b = hi;
}

__global__ __launch_bounds__(128) void glimpse_kernel(const float* __restrict__ coords,
                                                      const float* __restrict__ mask,
                                                      const int* __restrict__ last) {
    __shared__ unsigned long long warp16[4][16];
    __shared__ int   sel[KNB];
    __shared__ float vsh[KNB*128];
    __shared__ float ssc[128];
    __shared__ float wsh[128];
    int g = blockIdx.x, b = blockIdx.y;
    int tid = threadIdx.x, lane = tid & 31, w = tid >> 5;

    int idxLast = last[b*Gg + g];
    float lx = coords[((size_t)b*Nn + idxLast)*2 + 0];
    float ly = coords[((size_t)b*Nn + idxLast)*2 + 1];

    // each thread builds 4 packed keys (dist_bits<<32 | n); OOB/masked -> huge
    unsigned long long k0, k1, k2, k3;
    {
        const float* mrow = mask + ((size_t)b*Gg + g)*Nn;
        unsigned long long kk[4];
#pragma unroll
        for (int i = 0; i < 4; ++i) {
            int n = w*128 + lane + 32*i;
            unsigned long long key = ~0ull;
            if (n < Nn) {
                float m = mrow[n];
                if (m == -INFINITY) {
                    key = (0x7F800000ull << 32) | (unsigned)n;   // +inf distance
                } else {
                    float dx = lx - coords[((size_t)b*Nn + n)*2 + 0];
                    float dy = ly - coords[((size_t)b*Nn + n)*2 + 1];
                    float d = sqrtf(dx*dx + dy*dy);
                    key = ((unsigned long long)__float_as_uint(d) << 32) | (unsigned)n;
                }
            }
            kk[i] = key;
        }
        k0 = kk[0]; k1 = kk[1]; k2 = kk[2]; k3 = kk[3];
        // sort 4 ascending (network)
        cswap(k0, k1); cswap(k2, k3); cswap(k0, k2); cswap(k1, k3); cswap(k1, k2);
    }

    // warp-local top-16: 16 butterfly-min passes over sorted heads (no block barriers)
#pragma unroll
    for (int it = 0; it < KNB; ++it) {
        unsigned long long key = k0;
#pragma unroll
        for (int off = 16; off; off >>= 1)
            key = min(key, __shfl_xor_sync(0xffffffffu, key, off));
        if (k0 == key) { k0 = k1; k1 = k2; k2 = k3; k3 = ~0ull; }  // unique keys: one winner
        if (lane == 0) warp16[w][it] = key;
    }
    __syncthreads();

    // serial 4-way merge of sorted 16-lists -> global top-16 (exact, tie-safe)
    if (tid == 0) {
        int p0 = 0, p1 = 0, p2 = 0, p3 = 0;
#pragma unroll
        for (int it = 0; it < KNB; ++it) {
            unsigned long long c0 = warp16[0][p0], c1 = warp16[1][p1];
            unsigned long long c2 = warp16[2][p2], c3 = warp16[3][p3];
            unsigned long long m01 = min(c0, c1), m23 = min(c2, c3);
            unsigned long long m = min(m01, m23);
            sel[it] = (int)(m & 0xffffffffu);
            if (m == c0) ++p0; else if (m == c1) ++p1; else if (m == c2) ++p2; else ++p3;
        }
    }
    __syncthreads();

    // sparse attention over the 16 selected keys
    float qv = g_Q[((size_t)b*Gg + g)*Hh + tid];
#pragma unroll
    for (int j = 0; j < KNB; ++j) {
        int n = sel[j];
        size_t base = ((size_t)b*Nn + n)*Hh;
        float kv = g_K[base + tid];
        vsh[j*128 + tid] = g_V[base + tid];
        float p = qv * kv;
        p += __shfl_xor_sync(0xffffffffu, p, 8, 16);
        p += __shfl_xor_sync(0xffffffffu, p, 4, 16);
        p += __shfl_xor_sync(0xffffffffu, p, 2, 16);
        p += __shfl_xor_sync(0xffffffffu, p, 1, 16);
        if ((tid & 15) == 0) ssc[(tid >> 4)*16 + j] = p * 0.25f;
    }
    __syncthreads();

    if (tid < 8) {
        float mx = -INFINITY;
#pragma unroll
        for (int j = 0; j < KNB; ++j) mx = fmaxf(mx, ssc[tid*16 + j]);
        float s = 0.f;
#pragma unroll
        for (int j = 0; j < KNB; ++j) { float e = __expf(ssc[tid*16 + j] - mx); wsh[tid*16 + j] = e; s += e; }
        float inv = 1.f / s;
#pragma unroll
        for (int j = 0; j < KNB; ++j) wsh[tid*16 + j] *= inv;
    }
    __syncthreads();

    int h = tid >> 4;
    float o = 0.f;
#pragma unroll
    for (int j = 0; j < KNB; ++j) o += wsh[h*16 + j] * vsh[j*128 + tid];
    g_attnT[(size_t)b*Hh*Gg + tid*Gg + g] = o;
}

// ---------------- F1: pointer GEMM + tanh + mask -> scores in out ----------------
__global__ __launch_bounds__(256, 2) void final_gemm_kernel(const float* __restrict__ mask,
                                                            float* __restrict__ out) {
    extern __shared__ float sm[];
    float* As = sm;
    float* Bs = sm + 8192;
    int b = blockIdx.z, n0 = blockIdx.x * 128, g0 = blockIdx.y * 128;
    int tid = threadIdx.x;
    int ty = tid >> 4, tx = tid & 15;
    unsigned long long acc[4][8];
#pragma unroll
    for (int rp = 0; rp < 4; ++rp)
#pragma unroll
        for (int c = 0; c < 8; ++c) acc[rp][c] = 0ull;

    const float* attnTb = g_attnT + (size_t)b*Hh*Gg;
    const float* EpTb   = g_EpT   + (size_t)b*Hh*Nn;
#pragma unroll
    for (int kc = 0; kc < 2; ++kc) {
        fill_k(As, attnTb, Gg, g0, Gg, kc, tid);
        fill_k(Bs, EpTb,   Nn, n0, Nn, kc, tid);
        __syncthreads();
        mm64(As, Bs, ty, tx, acc);
        __syncthreads();
    }
    float accf[8][8];
    unpack_acc(acc, accf);

    float be[8];
#pragma unroll
    for (int q = 0; q < 8; ++q) {
        int n = n0 + tx*8 + q;
        be[q] = (n < Nn) ? g_biasE[b*Nn + n] : 0.f;
    }
#pragma unroll
    for (int p = 0; p < 8; ++p) {
        int g = g0 + ty*8 + p;
        if (g >= Gg) continue;
        const float* mrow = mask + ((size_t)b*Gg + g)*Nn;
        float* orow = out + ((size_t)b*Gg + g)*Nn;
#pragma unroll
        for (int q = 0; q < 8; ++q) {
            int n = n0 + tx*8 + q;
            if (n >= Nn) continue;
            float s = accf[p][q] + be[q];
            orow[n] = fast_tanh(s) * 10.0f + mrow[n];
        }
    }
}

// ---------------- F2: warp-per-row softmax, in place on out ----------------
__global__ __launch_bounds__(256) void softmax_kernel(float* __restrict__ out) {
    int warp = threadIdx.x >> 5, lane = threadIdx.x & 31;
    int r = blockIdx.x * 8 + warp;
    if (r >= Bsz*Gg) return;
    float* row = out + (size_t)r*Nn;
    float v[16];
    float m = -INFINITY;
#pragma unroll
    for (int i = 0; i < 16; ++i) {
        int n = lane + i*32;
        v[i] = (n < Nn) ? row[n] : -INFINITY;
        m = fmaxf(m, v[i]);
    }
    for (int off = 16; off; off >>= 1) m = fmaxf(m, __shfl_xor_sync(0xffffffffu, m, off));
    float s = 0.f;
#pragma unroll
    for (int i = 0; i < 16; ++i) { float e = __expf(v[i] - m); v[i] = e; s += e; }
    for (int off = 16; off; off >>= 1) s += __shfl_xor_sync(0xffffffffu, s, off);
    float inv = 1.f / s;
#pragma unroll
    for (int i = 0; i < 16; ++i) {
        int n = lane + i*32;
        if (n < Nn) row[n] = v[i] * inv;
    }
}

// ---------------- host ----------------
extern "C" void kernel_launch(void* const* d_in, const int* in_sizes, int n_in,
                              void* d_out, int out_size) {
    const float* coords   = (const float*)d_in[0];
    const float* emb      = (const float*)d_in[1];
    const int*   last     = (const int*)  d_in[2];
    const float* mask     = (const float*)d_in[3];
    const float* Wq_graph = (const float*)d_in[4];
    const float* Wq_first = (const float*)d_in[5];
    const float* Wq_last  = (const float*)d_in[6];
    const float* Wk       = (const float*)d_in[7];
    const float* Wv       = (const float*)d_in[8];
    const float* Wc       = (const float*)d_in[9];
    const float* bc       = (const float*)d_in[10];
    float* out = (float*)d_out;

    cudaFuncSetAttribute(gemms_kernel,      cudaFuncAttributeMaxDynamicSharedMemorySize, 66048);
    cudaFuncSetAttribute(final_gemm_kernel, cudaFuncAttributeMaxDynamicSharedMemorySize, 65536);

    prep1_kernel<<<256, 256>>>(Wk, Wv, Wc, Wq_first, Wq_last);
    prep2_kernel<<<4096, 256>>>(emb, bc, last);
    gemms_kernel<<<512, 256, 66048>>>(Wq_graph);
    glimpse_kernel<<<dim3(Gg, Bsz), 128>>>(coords, mask, last);
    final_gemm_kernel<<<dim3(4, 4, Bsz), 256, 65536>>>(mask, out);
    softmax_kernel<<<2000, 256>>>(out);
}